// round 13
// baseline (speedup 1.0000x reference)
#include <cuda_runtime.h>
#include <cuda_bf16.h>

// TSAdaptivePatcher: PATCH_SIZE == STRIDE == 16 -> non-overlapping windows.
//   x:    [B=64, C=64, S=8192] f32
//   mask: [B=64, S=8192] i32 (0/1)
// Outputs (concatenated in d_out, f32):
//   patches      [B, 512, 1024] : patches[b,p,c*16+j] = x[b,c,p*16+j]
//   padding_mask [B, 512]       : (sum_{j<16} mask[b,p*16+j] >= 8) ? 1 : 0
//
// R10: persistent single-wave copy. R5-R9 established the DRAM mixed-stream
// ceiling (~6TB/s, dram%~75) is invariant to ILP/width/policy; the one
// unattacked model term is wave-transition + tail cost (4096 tile-blocks =
// ~4.7 waves -> ~4 x 2360cyc transitions + last-wave spread). Here: 888
// persistent copy blocks (148 SMs x 6 resident) grid-stride over the 4096
// tiles. Tile interior byte-identical to the best (R5) kernel: float4,
// ILP=8, 512B/thread contiguous reads, linear writes, __ldcs/__stcs.
// Mask blocks fused at low blockIdx (finish in wave 1, hidden).

static constexpr int B = 64;
static constexpr int C = 64;
static constexpr int S = 8192;
static constexpr int NPATCH = 512;
static constexpr long PATCH_ELEMS = (long)B * NPATCH * C * 16;   // 33,554,432
static constexpr int N_COPY_V4 = (int)(PATCH_ELEMS / 4);         // 8,388,608 = 2^23
static constexpr int N_MASK = B * NPATCH;                        // 32,768

static constexpr int TPB = 256;
static constexpr int ILP = 8;
static constexpr int TILE_V4 = TPB * ILP;                        // 2048 float4 / tile
static constexpr int N_TILES = N_COPY_V4 / TILE_V4;              // 4096
static constexpr int COPY_BLOCKS = 148 * 6;                      // 888: one wave
static constexpr int MASK_BLOCKS = N_MASK / TPB;                 // 128

__global__ void __launch_bounds__(TPB) fused_patcher_kernel(
    const float4* __restrict__ x,
    const int4*   __restrict__ mask,
    float4* __restrict__ out_patches,
    float*  __restrict__ out_mask)
{
    int bid = blockIdx.x;

    if (bid < MASK_BLOCKS) {
        // ---- mask reduction: i = b*512 + p ----
        int i = bid * TPB + threadIdx.x;
        const int4* mp = mask + (i << 2);        // 16 contiguous ints per patch
        int s = 0;
#pragma unroll
        for (int k = 0; k < 4; k++) {
            int4 v = __ldcs(mp + k);
            s += v.x + v.y + v.z + v.w;
        }
        // valid_ratio >= 0.5  <=>  integer sum >= 8 (exact)
        out_mask[i] = (s >= 8) ? 1.0f : 0.0f;
        return;
    }

    // ---- persistent streaming permutation: grid-stride over tiles ----
    for (int tile = bid - MASK_BLOCKS; tile < N_TILES; tile += COPY_BLOCKS) {
        int base = tile * TILE_V4 + threadIdx.x; // output-linear float4 index

        // out bits: [b:6][p:9][c:6][jv:2]; i += 256 increments p ->
        // src advances 4 float4s (64B): per-thread reads are contiguous 512B.
        int jv = base & 3;
        int c  = (base >> 2) & 63;
        int p  = (base >> 8) & 511;
        int b  = base >> 17;
        int src0 = (((b << 6) + c) << 11) + (p << 2) + jv;

        float4 v[ILP];
#pragma unroll
        for (int k = 0; k < ILP; k++)
            v[k] = __ldcs(x + src0 + k * 4);     // 8 independent 64B loads
#pragma unroll
        for (int k = 0; k < ILP; k++)
            __stcs(out_patches + base + k * TPB, v[k]);
    }
}

extern "C" void kernel_launch(void* const* d_in, const int* in_sizes, int n_in,
                              void* d_out, int out_size)
{
    (void)in_sizes; (void)n_in; (void)out_size;
    const float4* x    = (const float4*)d_in[0];
    const int4*   mask = (const int4*)d_in[1];
    float* out = (float*)d_out;

    fused_patcher_kernel<<<MASK_BLOCKS + COPY_BLOCKS, TPB>>>(
        x, mask, (float4*)out, out + PATCH_ELEMS);
}

// round 16
// speedup vs baseline: 1.0908x; 1.0908x over previous
#include <cuda_runtime.h>
#include <cuda_bf16.h>

// TSAdaptivePatcher: PATCH_SIZE == STRIDE == 16 -> non-overlapping windows.
//   x:    [B=64, C=64, S=8192] f32
//   mask: [B=64, S=8192] i32 (0/1)
// Outputs (concatenated in d_out, f32):
//   patches      [B, 512, 1024] : patches[b,p,c*16+j] = x[b,c,p*16+j]
//   padding_mask [B, 512]       : (sum_{j<16} mask[b,p*16+j] >= 8) ? 1 : 0
//
// FINAL (revert to R5, the best-measured config at 43.8us):
// Six structural variants (ILP 4/8, 128/256-bit, L2 evict policies, partial
// pinning, persistent single-wave) all pinned dram__cycles_active at 72-76%
// and kernel time at 36-38us -> the limiter is the DRAM controller on a 1:1
// read/write mixed stream (~6TB/s effective). This config measured best:
//  - single fused launch; mask blocks at low blockIdx (hidden under copy)
//  - copy: ILP=8 independent float4s/thread, k-stride = TPB, so each
//    thread reads 512B contiguous (p-field increment), writes fully linear
//  - __ldcs/__stcs streaming hints (zero reuse; working set >> L2)

static constexpr int B = 64;
static constexpr int C = 64;
static constexpr int S = 8192;
static constexpr int NPATCH = 512;
static constexpr long PATCH_ELEMS = (long)B * NPATCH * C * 16;   // 33,554,432
static constexpr int N_COPY_V4 = (int)(PATCH_ELEMS / 4);         // 8,388,608 = 2^23
static constexpr int N_MASK = B * NPATCH;                        // 32,768

static constexpr int TPB = 256;
static constexpr int ILP = 8;
static constexpr int COPY_BLOCKS = N_COPY_V4 / (TPB * ILP);      // 4096
static constexpr int MASK_BLOCKS = N_MASK / TPB;                 // 128

__global__ void __launch_bounds__(TPB) fused_patcher_kernel(
    const float4* __restrict__ x,
    const int4*   __restrict__ mask,
    float4* __restrict__ out_patches,
    float*  __restrict__ out_mask)
{
    int bid = blockIdx.x;

    if (bid < MASK_BLOCKS) {
        // ---- mask reduction: i = b*512 + p ----
        int i = bid * TPB + threadIdx.x;
        const int4* mp = mask + (i << 2);        // 16 contiguous ints per patch
        int s = 0;
#pragma unroll
        for (int k = 0; k < 4; k++) {
            int4 v = __ldcs(mp + k);
            s += v.x + v.y + v.z + v.w;
        }
        // valid_ratio >= 0.5  <=>  integer sum >= 8 (exact)
        out_mask[i] = (s >= 8) ? 1.0f : 0.0f;
        return;
    }

    // ---- streaming permutation, output-linear, ILP=8 ----
    int cb = bid - MASK_BLOCKS;
    int base = cb * (TPB * ILP) + threadIdx.x;

    // Decode source once; i += TPB(=256) increments the p field (bit 8),
    // so src advances by 4 float4s (64B) per k: contiguous per-thread reads.
    int i0 = base;
    int jv = i0 & 3;
    int c  = (i0 >> 2) & 63;
    int p  = (i0 >> 8) & 511;
    int b  = i0 >> 17;
    int src0 = (((b << 6) + c) << 11) + (p << 2) + jv;

    float4 v[ILP];
#pragma unroll
    for (int k = 0; k < ILP; k++)
        v[k] = __ldcs(x + src0 + k * 4);         // 8 independent, contiguous 64B
#pragma unroll
    for (int k = 0; k < ILP; k++)
        __stcs(out_patches + base + k * TPB, v[k]);
}

extern "C" void kernel_launch(void* const* d_in, const int* in_sizes, int n_in,
                              void* d_out, int out_size)
{
    (void)in_sizes; (void)n_in; (void)out_size;
    const float4* x    = (const float4*)d_in[0];
    const int4*   mask = (const int4*)d_in[1];
    float* out = (float*)d_out;

    fused_patcher_kernel<<<MASK_BLOCKS + COPY_BLOCKS, TPB>>>(
        x, mask, (float4*)out, out + PATCH_ELEMS);
}

// round 17
// speedup vs baseline: 1.1058x; 1.0137x over previous
#include <cuda_runtime.h>
#include <cuda_bf16.h>

// TSAdaptivePatcher: PATCH_SIZE == STRIDE == 16 -> non-overlapping windows.
//   x:    [B=64, C=64, S=8192] f32
//   mask: [B=64, S=8192] i32 (0/1)
// Outputs (concatenated in d_out, f32):
//   patches      [B, 512, 1024] : patches[b,p,c*16+j] = x[b,c,p*16+j]
//   padding_mask [B, 512]       : (sum_{j<16} mask[b,p*16+j] >= 8) ? 1 : 0
//
// CONVERGED CONFIG. Seven variants (ILP 4/8, 128/256-bit, L2 policies,
// partial pin, persistent single-wave) all sit at a ~44.5 +/- 1us plateau
// with dram__cycles_active 72-76%: the DRAM controller on a 1:1 r/w mixed
// stream (~5.9TB/s effective) is the wall; traffic (258MB) is minimal.
// This picks the best-secondary-indicator point on the plateau:
//  - ILP=4 (22-reg class -> ~75% occupancy, highest measured DRAM% 75.9)
//  - k-stride = TPB so the p-field increments: 256B contiguous per-thread
//    reads, fully linear writes (free, no register cost)
//  - single fused launch; mask blocks at low blockIdx, hidden under copy
//  - __ldcs/__stcs streaming hints (zero reuse; working set >> L2)

static constexpr int B = 64;
static constexpr int C = 64;
static constexpr int S = 8192;
static constexpr int NPATCH = 512;
static constexpr long PATCH_ELEMS = (long)B * NPATCH * C * 16;   // 33,554,432
static constexpr int N_COPY_V4 = (int)(PATCH_ELEMS / 4);         // 8,388,608 = 2^23
static constexpr int N_MASK = B * NPATCH;                        // 32,768

static constexpr int TPB = 256;
static constexpr int ILP = 4;
static constexpr int COPY_BLOCKS = N_COPY_V4 / (TPB * ILP);      // 8192
static constexpr int MASK_BLOCKS = N_MASK / TPB;                 // 128

__global__ void __launch_bounds__(TPB) fused_patcher_kernel(
    const float4* __restrict__ x,
    const int4*   __restrict__ mask,
    float4* __restrict__ out_patches,
    float*  __restrict__ out_mask)
{
    int bid = blockIdx.x;

    if (bid < MASK_BLOCKS) {
        // ---- mask reduction: i = b*512 + p ----
        int i = bid * TPB + threadIdx.x;
        const int4* mp = mask + (i << 2);        // 16 contiguous ints per patch
        int s = 0;
#pragma unroll
        for (int k = 0; k < 4; k++) {
            int4 v = __ldcs(mp + k);
            s += v.x + v.y + v.z + v.w;
        }
        // valid_ratio >= 0.5  <=>  integer sum >= 8 (exact)
        out_mask[i] = (s >= 8) ? 1.0f : 0.0f;
        return;
    }

    // ---- streaming permutation, output-linear, ILP=4 ----
    int cb = bid - MASK_BLOCKS;
    int base = cb * (TPB * ILP) + threadIdx.x;

    // Decode source once; i += TPB(=256) increments the p field (bit 8),
    // so src advances by 4 float4s (64B) per k: contiguous per-thread reads.
    int jv = base & 3;
    int c  = (base >> 2) & 63;
    int p  = (base >> 8) & 511;
    int b  = base >> 17;
    int src0 = (((b << 6) + c) << 11) + (p << 2) + jv;

    float4 v[ILP];
#pragma unroll
    for (int k = 0; k < ILP; k++)
        v[k] = __ldcs(x + src0 + k * 4);         // 4 independent, contiguous 64B
#pragma unroll
    for (int k = 0; k < ILP; k++)
        __stcs(out_patches + base + k * TPB, v[k]);
}

extern "C" void kernel_launch(void* const* d_in, const int* in_sizes, int n_in,
                              void* d_out, int out_size)
{
    (void)in_sizes; (void)n_in; (void)out_size;
    const float4* x    = (const float4*)d_in[0];
    const int4*   mask = (const int4*)d_in[1];
    float* out = (float*)d_out;

    fused_patcher_kernel<<<MASK_BLOCKS + COPY_BLOCKS, TPB>>>(
        x, mask, (float4*)out, out + PATCH_ELEMS);
}